// round 17
// baseline (speedup 1.0000x reference)
#include <cuda_runtime.h>
#include <cuda_fp16.h>
#include <cstdint>

#define Bd 256
#define Sd 512
#define Cd 64
#define Hd 128
#define Gd 512
#define REC_THREADS 512

typedef unsigned long long u64;
typedef unsigned int u32;

// ---------------- device global scratch ----------------
__device__ __half g_xg[(size_t)Sd * Bd * Gd];     // gate preacts, fp16
__device__ __half g_a0[(size_t)Sd * Bd * Cd];     // x, fp16, m-major
__device__ __half g_y1h[(size_t)Sd * Bd * Hd];    // layer-0 h, fp16, m-major
__device__ __half g_w0h[(size_t)Gd * Cd];         // Wih0 fp16
__device__ __half g_w1h[(size_t)Gd * Hd];         // Wih1 fp16
__device__ float  g_bs0[Gd];
__device__ float  g_bs1[Gd];

// ---------------- helpers ----------------
__device__ __forceinline__ float tanh_fast(float x) {
    float y; asm("tanh.approx.f32 %0, %1;" : "=f"(y) : "f"(x)); return y;
}
__device__ __forceinline__ void mma_f16(
    float& c0, float& c1, float& c2, float& c3,
    u32 a0, u32 a1, u32 a2, u32 a3, u32 b0, u32 b1)
{
    asm("mma.sync.aligned.m16n8k16.row.col.f32.f16.f16.f32 "
        "{%0,%1,%2,%3}, {%4,%5,%6,%7}, {%8,%9}, {%0,%1,%2,%3};"
        : "+f"(c0), "+f"(c1), "+f"(c2), "+f"(c3)
        : "r"(a0), "r"(a1), "r"(a2), "r"(a3), "r"(b0), "r"(b1));
}
__device__ __forceinline__ void cp16(u32 dst, const void* src) {
    asm volatile("cp.async.cg.shared.global [%0], [%1], 16;" :: "r"(dst), "l"(src));
}
__device__ __forceinline__ u32 smem_u32(const void* p) {
    u32 a; asm("{ .reg .u64 t; cvta.to.shared.u64 t, %1; cvt.u32.u64 %0, t; }" : "=r"(a) : "l"(p));
    return a;
}

// ---------------- prep kernels ----------------
__global__ void prep_x_kernel(const float* __restrict__ x)
{
    int i = blockIdx.x * 256 + threadIdx.x;
    if (i >= Bd * Sd * Cd) return;
    int k = i & (Cd - 1);
    int s = (i >> 6) & (Sd - 1);
    int b = i >> 15;
    g_a0[((size_t)(s * Bd + b)) * Cd + k] = __float2half(x[i]);
}

__global__ void prep_w_kernel(const float* __restrict__ W, const float* __restrict__ b1,
                              const float* __restrict__ b2, __half* __restrict__ wh,
                              float* __restrict__ bsum, int n)
{
    int i = blockIdx.x * 256 + threadIdx.x;
    if (i >= n) return;
    wh[i] = __float2half(W[i]);
    if (i < Gd) bsum[i] = b1[i] + b2[i];
}

// ---------------------------------------------------------------------------
// Pipelined FP16 GEMM (fp32 accum) — unchanged (round-13 proven).
// ---------------------------------------------------------------------------
template <int K>
__global__ __launch_bounds__(256) void gemm_f16_kernel(
    const __half* __restrict__ A, const __half* __restrict__ Wh,
    const float* __restrict__ bsum, __half* __restrict__ out)
{
    constexpr int KC = 32;
    constexpr int NC = K / KC;
    constexpr int SKW = 20;
    constexpr int TBUF = 128 * SKW;

    extern __shared__ u32 sm32[];
    const u32 sb = smem_u32(sm32);

    const int tid = threadIdx.x;
    const int mt  = blockIdx.x;
    const int nt  = blockIdx.y;

    auto fill = [&](int c, int buf) {
        const int k0 = c * KC;
#pragma unroll
        for (int r = 0; r < 2; r++) {
            int task = tid + 256 * r;
            int row = task >> 2, seg = task & 3;
            cp16(sb + (u32)(buf * 2 * TBUF + row * SKW + seg * 4) * 4,
                 (const char*)(A + (size_t)(mt * 128 + row) * K + k0) + seg * 16);
        }
#pragma unroll
        for (int r = 0; r < 2; r++) {
            int task = tid + 256 * r;
            int row = task >> 2, seg = task & 3;
            cp16(sb + (u32)(buf * 2 * TBUF + TBUF + row * SKW + seg * 4) * 4,
                 (const char*)(Wh + (size_t)(nt * 128 + row) * K + k0) + seg * 16);
        }
        asm volatile("cp.async.commit_group;" ::: "memory");
    };

    const int wid  = tid >> 5;
    const int lane = tid & 31;
    const int gID  = lane >> 2;
    const int tig  = lane & 3;
    const int wm   = (wid >> 1) * 32;
    const int wn   = (wid & 1) * 64;

    float c[2][8][4];
#pragma unroll
    for (int i = 0; i < 2; i++)
#pragma unroll
        for (int j = 0; j < 8; j++)
#pragma unroll
            for (int q = 0; q < 4; q++) c[i][j][q] = 0.0f;

    fill(0, 0);

    for (int ch = 0; ch < NC; ch++) {
        if (ch + 1 < NC) {
            fill(ch + 1, (ch + 1) & 1);
            asm volatile("cp.async.wait_group 1;" ::: "memory");
        } else {
            asm volatile("cp.async.wait_group 0;" ::: "memory");
        }
        __syncthreads();

        const u32* As = sm32 + (ch & 1) * 2 * TBUF;
        const u32* Bs = As + TBUF;

#pragma unroll
        for (int ks = 0; ks < KC / 16; ks++) {
            const int kw = ks * 8;
            u32 a[2][4];
#pragma unroll
            for (int mi = 0; mi < 2; mi++) {
                int r = wm + mi * 16 + gID;
                a[mi][0] = As[r * SKW + kw + tig];
                a[mi][1] = As[(r + 8) * SKW + kw + tig];
                a[mi][2] = As[r * SKW + kw + tig + 4];
                a[mi][3] = As[(r + 8) * SKW + kw + tig + 4];
            }
            u32 b[8][2];
#pragma unroll
            for (int ni = 0; ni < 8; ni++) {
                int r = wn + ni * 8 + gID;
                b[ni][0] = Bs[r * SKW + kw + tig];
                b[ni][1] = Bs[r * SKW + kw + tig + 4];
            }
#pragma unroll
            for (int mi = 0; mi < 2; mi++)
#pragma unroll
                for (int ni = 0; ni < 8; ni++)
                    mma_f16(c[mi][ni][0], c[mi][ni][1], c[mi][ni][2], c[mi][ni][3],
                            a[mi][0], a[mi][1], a[mi][2], a[mi][3],
                            b[ni][0], b[ni][1]);
        }
        __syncthreads();
    }

#pragma unroll
    for (int ni = 0; ni < 8; ni++) {
        int g = nt * 128 + wn + ni * 8 + 2 * tig;
        float2 bv = *(const float2*)&bsum[g];
#pragma unroll
        for (int mi = 0; mi < 2; mi++) {
            size_t m = (size_t)mt * 128 + wm + mi * 16 + gID;
            *(__half2*)&out[m * Gd + g] =
                __floats2half2_rn(c[mi][ni][0] + bv.x, c[mi][ni][1] + bv.y);
            *(__half2*)&out[(m + 8) * Gd + g] =
                __floats2half2_rn(c[mi][ni][2] + bv.x, c[mi][ni][3] + bv.y);
        }
    }
}

// ---------------------------------------------------------------------------
// LSTM recurrence v6: 512 threads, quad-per-unit layout, register fp16
// weights (r16 proven) + shortened epilogue: hadd2 reduction tree
// (2 hadd2 + 2 converts + 3 fadds per batch) and no final-step barrier.
// ---------------------------------------------------------------------------
#define HROW 144
#define SMEM_REC (2 * 2 * HROW * 2)           // 1152 B

template <bool YIMG>
__global__ __launch_bounds__(REC_THREADS, 1) void lstm_rec_kernel(
    const __half* __restrict__ xg, const float* __restrict__ Whh,
    __half* __restrict__ y_img, float* __restrict__ y_last)
{
    extern __shared__ char smraw[];
    __half* hb = (__half*)smraw;              // [2 phase][2 batch][HROW]

    const int t = threadIdx.x;
    const int r = t & 3;                      // gate index (0=i,1=f,2=g,3=o)
    const int u = t >> 2;                     // hidden unit
    const int col = r * Hd + u;               // gate column in xg / Whh row
    const int b0 = blockIdx.x * 2;
    const int qb = (t & 31) & ~3;             // quad base lane

    // Full weight row in registers: 64 fp16 pairs.
    u32 w2[64];
#pragma unroll
    for (int j = 0; j < 64; j++) {
        __half2 a = __floats2half2_rn(Whh[(size_t)col * Hd + 2 * j],
                                      Whh[(size_t)col * Hd + 2 * j + 1]);
        w2[j] = *(u32*)&a;
    }
    for (int i = t; i < 2 * 2 * HROW; i += REC_THREADS) hb[i] = __half(0.0f);

    float c = 0.0f;
    __syncthreads();

    __half xh0 = xg[(size_t)(b0)*Gd + col];
    __half xh1 = xg[(size_t)(b0 + 1) * Gd + col];

    for (int s = 0; s < Sd; s++) {
        __half nx0, nx1;
        if (s + 1 < Sd) {
            size_t base = (size_t)(s + 1) * Bd + b0;
            nx0 = xg[base * Gd + col];
            nx1 = xg[(base + 1) * Gd + col];
        } else {
            nx0 = nx1 = __half(0.0f);
        }
        const int ph = s & 1;
        const ulonglong2* hq0 = (const ulonglong2*)(hb + (ph * 2 + 0) * HROW);
        const ulonglong2* hq1 = (const ulonglong2*)(hb + (ph * 2 + 1) * HROW);

        // 4 interleaved half2 chains per batch (16 terms each)
        __half2 z = __floats2half2_rn(0.0f, 0.0f);
        __half2 a0[4] = {z, z, z, z};
        __half2 a1[4] = {z, z, z, z};

#pragma unroll
        for (int q = 0; q < 16; q++) {        // 16B quads: 4 half2 each
            ulonglong2 q0 = hq0[q];
            ulonglong2 q1 = hq1[q];
            const __half2* h0 = (const __half2*)&q0;
            const __half2* h1 = (const __half2*)&q1;
#pragma unroll
            for (int j2 = 0; j2 < 4; j2++) {
                __half2 w = *(const __half2*)&w2[q * 4 + j2];
                a0[j2] = __hfma2(w, h0[j2], a0[j2]);
                a1[j2] = __hfma2(w, h1[j2], a1[j2]);
            }
        }

        // shortened reduction: one hadd2 level, then fp32
        __half2 s0a = __hadd2(a0[0], a0[1]);
        __half2 s0b = __hadd2(a0[2], a0[3]);
        __half2 s1a = __hadd2(a1[0], a1[1]);
        __half2 s1b = __hadd2(a1[2], a1[3]);
        float2 f0a = __half22float2(s0a), f0b = __half22float2(s0b);
        float2 f1a = __half22float2(s1a), f1b = __half22float2(s1b);

        float p0 = __half2float(xh0) + ((f0a.x + f0a.y) + (f0b.x + f0b.y));
        float p1 = __half2float(xh1) + ((f1a.x + f1a.y) + (f1b.x + f1b.y));

        // activation: r==2 (g gate) tanh, else sigmoid
        float s0 = (r == 2) ? p0 : 0.5f * p0;
        float s1 = (r == 2) ? p1 : 0.5f * p1;
        float t0 = tanh_fast(s0);
        float t1 = tanh_fast(s1);
        float v0 = (r == 2) ? t0 : fmaf(0.5f, t0, 0.5f);
        float v1 = (r == 2) ? t1 : fmaf(0.5f, t1, 0.5f);

        // quad transpose via shfl (i,f,g,o for both batches)
        float i0 = __shfl_sync(0xffffffffu, v0, qb + 0);
        float ff0 = __shfl_sync(0xffffffffu, v0, qb + 1);
        float gg0 = __shfl_sync(0xffffffffu, v0, qb + 2);
        float o0 = __shfl_sync(0xffffffffu, v0, qb + 3);
        float i1 = __shfl_sync(0xffffffffu, v1, qb + 0);
        float ff1 = __shfl_sync(0xffffffffu, v1, qb + 1);
        float gg1 = __shfl_sync(0xffffffffu, v1, qb + 2);
        float o1 = __shfl_sync(0xffffffffu, v1, qb + 3);

        // lane r==0 owns batch0; lane r==1 owns batch1
        float iv = (r == 0) ? i0 : i1;
        float fv = (r == 0) ? ff0 : ff1;
        float gv = (r == 0) ? gg0 : gg1;
        float ov = (r == 0) ? o0 : o1;
        c = fmaf(fv, c, iv * gv);
        float hn = ov * tanh_fast(c);

        if (r < 2) {
            __half hn16 = __float2half(hn);
            hb[((ph ^ 1) * 2 + r) * HROW + u] = hn16;
            if (YIMG) {
                y_img[((size_t)s * Bd + b0 + r) * Hd + u] = hn16;
            } else if (s == Sd - 1) {
                y_last[(size_t)(b0 + r) * Hd + u] = hn;
            }
        }

        xh0 = nx0; xh1 = nx1;
        if (s + 1 < Sd) __syncthreads();
    }
}

// ---------------------------------------------------------------------------
extern "C" void kernel_launch(void* const* d_in, const int* in_sizes, int n_in,
                              void* d_out, int out_size)
{
    const float* x    = (const float*)d_in[0];
    const float* Wih0 = (const float*)d_in[1];
    const float* Whh0 = (const float*)d_in[2];
    const float* bih0 = (const float*)d_in[3];
    const float* bhh0 = (const float*)d_in[4];
    const float* Wih1 = (const float*)d_in[5];
    const float* Whh1 = (const float*)d_in[6];
    const float* bih1 = (const float*)d_in[7];
    const float* bhh1 = (const float*)d_in[8];
    float* out = (float*)d_out;

    __half *xg, *a0, *y1h, *w0h, *w1h;
    float *bs0, *bs1;
    cudaGetSymbolAddress((void**)&xg, g_xg);
    cudaGetSymbolAddress((void**)&a0, g_a0);
    cudaGetSymbolAddress((void**)&y1h, g_y1h);
    cudaGetSymbolAddress((void**)&w0h, g_w0h);
    cudaGetSymbolAddress((void**)&w1h, g_w1h);
    cudaGetSymbolAddress((void**)&bs0, g_bs0);
    cudaGetSymbolAddress((void**)&bs1, g_bs1);

    const int smem_gemm = 2 * 2 * 128 * 20 * 4;   // 40960 B

    cudaFuncSetAttribute((const void*)gemm_f16_kernel<Cd>,
                         cudaFuncAttributeMaxDynamicSharedMemorySize, smem_gemm);
    cudaFuncSetAttribute((const void*)gemm_f16_kernel<Hd>,
                         cudaFuncAttributeMaxDynamicSharedMemorySize, smem_gemm);
    cudaFuncSetAttribute((const void*)lstm_rec_kernel<true>,
                         cudaFuncAttributeMaxDynamicSharedMemorySize, SMEM_REC);
    cudaFuncSetAttribute((const void*)lstm_rec_kernel<false>,
                         cudaFuncAttributeMaxDynamicSharedMemorySize, SMEM_REC);

    prep_x_kernel<<<(Bd * Sd * Cd + 255) / 256, 256>>>(x);
    prep_w_kernel<<<(Gd * Cd + 255) / 256, 256>>>(Wih0, bih0, bhh0, w0h, bs0, Gd * Cd);
    prep_w_kernel<<<(Gd * Hd + 255) / 256, 256>>>(Wih1, bih1, bhh1, w1h, bs1, Gd * Hd);

    dim3 ggrid((Sd * Bd) / 128, Gd / 128);

    // layer 0
    gemm_f16_kernel<Cd><<<ggrid, 256, smem_gemm>>>(a0, w0h, bs0, xg);
    lstm_rec_kernel<true><<<Bd / 2, REC_THREADS, SMEM_REC>>>(xg, Whh0, y1h, nullptr);

    // layer 1
    gemm_f16_kernel<Hd><<<ggrid, 256, smem_gemm>>>(y1h, w1h, bs1, xg);
    lstm_rec_kernel<false><<<Bd / 2, REC_THREADS, SMEM_REC>>>(xg, Whh1, nullptr, out);
}